// round 3
// baseline (speedup 1.0000x reference)
#include <cuda_runtime.h>

#define B_ 4
#define T_ 4096
#define C_ 1024
#define H_ 128
#define M_ (B_ * T_)

// Scratch for projections (no cudaMalloc allowed)
__device__ float g_k[M_ * H_];
__device__ float g_q[M_ * H_];
__device__ float g_v[M_ * H_];

// ---------------------------------------------------------------------------
// Projection GEMM: out[w] = x @ W[w], M=16384, N=128, K=1024
// BM=128, BN=128, BK=16, 256 threads, 8x8 micro-tile per thread.
// ---------------------------------------------------------------------------
__global__ __launch_bounds__(256, 1) void proj_kernel(
    const float* __restrict__ x, const float* __restrict__ Wk,
    const float* __restrict__ Wq, const float* __restrict__ Wv)
{
    const int w = blockIdx.y;
    const float* __restrict__ W = (w == 0) ? Wk : (w == 1) ? Wq : Wv;
    float* __restrict__ out = (w == 0) ? g_k : (w == 1) ? g_q : g_v;
    const int m0 = blockIdx.x * 128;

    __shared__ float Xs[16][132];  // transposed x tile: Xs[k][m]
    __shared__ float Ws[16][132];  // Ws[k][n]

    const int tid = threadIdx.x;
    const int tr = tid >> 4;   // 0..15 row group
    const int tc = tid & 15;   // 0..15 col group

    float acc[8][8];
#pragma unroll
    for (int i = 0; i < 8; i++)
#pragma unroll
        for (int j = 0; j < 8; j++) acc[i][j] = 0.f;

    for (int k0 = 0; k0 < C_; k0 += 16) {
        // Load x tile (128 rows x 16 k), store transposed
#pragma unroll
        for (int i = 0; i < 2; i++) {
            int idx = i * 256 + tid;         // 0..511 float4s
            int row = idx >> 2;              // 0..127
            int kc = (idx & 3) * 4;          // 0,4,8,12
            float4 v4 = *(const float4*)(x + (size_t)(m0 + row) * C_ + k0 + kc);
            Xs[kc + 0][row] = v4.x;
            Xs[kc + 1][row] = v4.y;
            Xs[kc + 2][row] = v4.z;
            Xs[kc + 3][row] = v4.w;
        }
        // Load W tile (16 k x 128 n)
#pragma unroll
        for (int i = 0; i < 2; i++) {
            int idx = i * 256 + tid;
            int kr = idx >> 5;               // 0..15
            int nc = (idx & 31) * 4;         // 0..124
            *(float4*)&Ws[kr][nc] = *(const float4*)(W + (size_t)(k0 + kr) * H_ + nc);
        }
        __syncthreads();

#pragma unroll
        for (int kk = 0; kk < 16; kk++) {
            float a[8], bv[8];
            *(float4*)&a[0] = *(const float4*)&Xs[kk][tr * 8];
            *(float4*)&a[4] = *(const float4*)&Xs[kk][tr * 8 + 4];
            *(float4*)&bv[0] = *(const float4*)&Ws[kk][tc * 8];
            *(float4*)&bv[4] = *(const float4*)&Ws[kk][tc * 8 + 4];
#pragma unroll
            for (int i = 0; i < 8; i++)
#pragma unroll
                for (int j = 0; j < 8; j++)
                    acc[i][j] = fmaf(a[i], bv[j], acc[i][j]);
        }
        __syncthreads();
    }

#pragma unroll
    for (int i = 0; i < 8; i++) {
        int row = m0 + tr * 8 + i;
        float4 o0 = make_float4(acc[i][0], acc[i][1], acc[i][2], acc[i][3]);
        float4 o1 = make_float4(acc[i][4], acc[i][5], acc[i][6], acc[i][7]);
        *(float4*)(out + (size_t)row * H_ + tc * 8) = o0;
        *(float4*)(out + (size_t)row * H_ + tc * 8 + 4) = o1;
    }
}

// ---------------------------------------------------------------------------
// Flash attention. Query role = k-projection, key role = q-projection.
// CTA: 64 query rows; loop over 64-row key/value tiles up to the causal limit.
// 256 threads: ty=tid/16 owns rows ty*4..+4, tx=tid%16 owns S-cols tx*4..+4
// and out-cols tx*8..+8. Online softmax with 16-lane shfl row reductions.
// ---------------------------------------------------------------------------
#define QS_STRIDE 132
#define KT_STRIDE 68
#define VS_STRIDE 132
#define PS_STRIDE 68

__global__ __launch_bounds__(256, 1) void attn_kernel(float* __restrict__ out)
{
    extern __shared__ float sm[];
    float* Qs  = sm;                        // [64][132] query tile (k matrix)
    float* KsT = Qs + 64 * QS_STRIDE;       // [128][68] key tile transposed
    float* Vs  = KsT + 128 * KT_STRIDE;     // [64][132] value tile
    float* Ps  = Vs + 64 * VS_STRIDE;       // [64][68]  softmax probs

    const int b  = blockIdx.x & 3;
    const int it = (T_ / 64 - 1) - (blockIdx.x >> 2);  // heavy tiles first
    const int i0 = it * 64;
    const size_t base = (size_t)b * T_ * H_;

    const int tid = threadIdx.x;
    const int ty = tid >> 4;
    const int tx = tid & 15;

    // Load query tile once (rows of g_k)
    for (int idx = tid; idx < 64 * 32; idx += 256) {
        int row = idx >> 5;
        int d4 = (idx & 31) * 4;
        *(float4*)&Qs[row * QS_STRIDE + d4] =
            *(const float4*)(g_k + base + (size_t)(i0 + row) * H_ + d4);
    }

    float m_i[4], l_i[4], acc[4][8];
#pragma unroll
    for (int i = 0; i < 4; i++) {
        m_i[i] = -1e30f;
        l_i[i] = 0.f;
#pragma unroll
        for (int c = 0; c < 8; c++) acc[i][c] = 0.f;
    }
    const float scale = 0.03125f;  // 1024^-0.5

    for (int jt = 0; jt <= it; jt++) {
        const int j0 = jt * 64;
        __syncthreads();  // prior-iter P@V done; Qs visible on first iter

        // Load key tile transposed (rows of g_q)
        for (int idx = tid; idx < 64 * 32; idx += 256) {
            int row = idx >> 5;
            int d4 = (idx & 31) * 4;
            float4 v4 = *(const float4*)(g_q + base + (size_t)(j0 + row) * H_ + d4);
            KsT[(d4 + 0) * KT_STRIDE + row] = v4.x;
            KsT[(d4 + 1) * KT_STRIDE + row] = v4.y;
            KsT[(d4 + 2) * KT_STRIDE + row] = v4.z;
            KsT[(d4 + 3) * KT_STRIDE + row] = v4.w;
        }
        // Load value tile
        for (int idx = tid; idx < 64 * 32; idx += 256) {
            int row = idx >> 5;
            int d4 = (idx & 31) * 4;
            *(float4*)&Vs[row * VS_STRIDE + d4] =
                *(const float4*)(g_v + base + (size_t)(j0 + row) * H_ + d4);
        }
        __syncthreads();

        // S = Q_tile @ K_tile^T : 4x4 micro-tile per thread
        float s[4][4];
#pragma unroll
        for (int i = 0; i < 4; i++)
#pragma unroll
            for (int c = 0; c < 4; c++) s[i][c] = 0.f;

#pragma unroll 8
        for (int d = 0; d < H_; d += 4) {
            float4 a[4], bb[4];
#pragma unroll
            for (int i = 0; i < 4; i++)
                a[i] = *(const float4*)&Qs[(ty * 4 + i) * QS_STRIDE + d];
#pragma unroll
            for (int j = 0; j < 4; j++)
                bb[j] = *(const float4*)&KsT[(d + j) * KT_STRIDE + tx * 4];
#pragma unroll
            for (int i = 0; i < 4; i++) {
                const float* av = (const float*)&a[i];
#pragma unroll
                for (int j = 0; j < 4; j++) {
                    const float* bv = (const float*)&bb[j];
                    s[i][0] = fmaf(av[j], bv[0], s[i][0]);
                    s[i][1] = fmaf(av[j], bv[1], s[i][1]);
                    s[i][2] = fmaf(av[j], bv[2], s[i][2]);
                    s[i][3] = fmaf(av[j], bv[3], s[i][3]);
                }
            }
        }

        // Scale + causal mask (only the diagonal tile can be partial)
        const bool diag = (jt == it);
#pragma unroll
        for (int i = 0; i < 4; i++)
#pragma unroll
            for (int c = 0; c < 4; c++) {
                float v = s[i][c] * scale;
                if (diag && (tx * 4 + c) > (ty * 4 + i)) v = -1e30f;
                s[i][c] = v;
            }

        // Online softmax per row (16 lanes per row-group share stats)
#pragma unroll
        for (int i = 0; i < 4; i++) {
            float tm = fmaxf(fmaxf(s[i][0], s[i][1]), fmaxf(s[i][2], s[i][3]));
#pragma unroll
            for (int off = 8; off > 0; off >>= 1)
                tm = fmaxf(tm, __shfl_xor_sync(0xffffffffu, tm, off, 16));
            float mnew = fmaxf(m_i[i], tm);
            float cf = __expf(m_i[i] - mnew);
            float ps = 0.f;
#pragma unroll
            for (int c = 0; c < 4; c++) {
                s[i][c] = __expf(s[i][c] - mnew);
                ps += s[i][c];
            }
#pragma unroll
            for (int off = 8; off > 0; off >>= 1)
                ps += __shfl_xor_sync(0xffffffffu, ps, off, 16);
            l_i[i] = l_i[i] * cf + ps;
            m_i[i] = mnew;
#pragma unroll
            for (int c = 0; c < 8; c++) acc[i][c] *= cf;
            *(float4*)&Ps[(ty * 4 + i) * PS_STRIDE + tx * 4] =
                make_float4(s[i][0], s[i][1], s[i][2], s[i][3]);
        }
        __syncthreads();

        // acc += P @ V : rows ty*4..+4, cols tx*8..+8
#pragma unroll 4
        for (int kk = 0; kk < 64; kk += 4) {
            float4 p[4];
#pragma unroll
            for (int i = 0; i < 4; i++)
                p[i] = *(const float4*)&Ps[(ty * 4 + i) * PS_STRIDE + kk];
#pragma unroll
            for (int j = 0; j < 4; j++) {
                float4 v0 = *(const float4*)&Vs[(kk + j) * VS_STRIDE + tx * 8];
                float4 v1 = *(const float4*)&Vs[(kk + j) * VS_STRIDE + tx * 8 + 4];
#pragma unroll
                for (int i = 0; i < 4; i++) {
                    float pv = ((const float*)&p[i])[j];
                    acc[i][0] = fmaf(pv, v0.x, acc[i][0]);
                    acc[i][1] = fmaf(pv, v0.y, acc[i][1]);
                    acc[i][2] = fmaf(pv, v0.z, acc[i][2]);
                    acc[i][3] = fmaf(pv, v0.w, acc[i][3]);
                    acc[i][4] = fmaf(pv, v1.x, acc[i][4]);
                    acc[i][5] = fmaf(pv, v1.y, acc[i][5]);
                    acc[i][6] = fmaf(pv, v1.z, acc[i][6]);
                    acc[i][7] = fmaf(pv, v1.w, acc[i][7]);
                }
            }
        }
    }

    // Epilogue: normalize and write
#pragma unroll
    for (int i = 0; i < 4; i++) {
        float inv = 1.0f / l_i[i];
        int row = i0 + ty * 4 + i;
        float4 o0 = make_float4(acc[i][0] * inv, acc[i][1] * inv,
                                acc[i][2] * inv, acc[i][3] * inv);
        float4 o1 = make_float4(acc[i][4] * inv, acc[i][5] * inv,
                                acc[i][6] * inv, acc[i][7] * inv);
        *(float4*)(out + base + (size_t)row * H_ + tx * 8) = o0;
        *(float4*)(out + base + (size_t)row * H_ + tx * 8 + 4) = o1;
    }
}

extern "C" void kernel_launch(void* const* d_in, const int* in_sizes, int n_in,
                              void* d_out, int out_size)
{
    const float* x  = (const float*)d_in[0];
    const float* Wk = (const float*)d_in[1];
    const float* Wq = (const float*)d_in[2];
    const float* Wv = (const float*)d_in[3];
    float* out = (float*)d_out;

    dim3 pgrid(M_ / 128, 3);
    proj_kernel<<<pgrid, 256>>>(x, Wk, Wq, Wv);

    const int smem_bytes =
        (64 * QS_STRIDE + 128 * KT_STRIDE + 64 * VS_STRIDE + 64 * PS_STRIDE) *
        (int)sizeof(float);
    // Idempotent; also set on the pre-capture correctness call so the
    // attribute is in place before graph capture. Return value ignored.
    cudaFuncSetAttribute(attn_kernel,
                         cudaFuncAttributeMaxDynamicSharedMemorySize, smem_bytes);
    attn_kernel<<<dim3((T_ / 64) * B_), 256, smem_bytes>>>(out);
}

// round 4
// speedup vs baseline: 2.1032x; 2.1032x over previous
#include <cuda_runtime.h>
#include <cstdint>

#define B_ 4
#define T_ 4096
#define C_ 1024
#define H_ 128
#define M_ (B_ * T_)

// Scratch for projections (no cudaMalloc allowed)
__device__ float g_k[M_ * H_];
__device__ float g_q[M_ * H_];
__device__ float g_v[M_ * H_];

// ---------------------------------------------------------------------------
// Projection GEMM (unchanged): out[w] = x @ W[w], M=16384, N=128, K=1024
// ---------------------------------------------------------------------------
__global__ __launch_bounds__(256, 1) void proj_kernel(
    const float* __restrict__ x, const float* __restrict__ Wk,
    const float* __restrict__ Wq, const float* __restrict__ Wv)
{
    const int w = blockIdx.y;
    const float* __restrict__ W = (w == 0) ? Wk : (w == 1) ? Wq : Wv;
    float* __restrict__ out = (w == 0) ? g_k : (w == 1) ? g_q : g_v;
    const int m0 = blockIdx.x * 128;

    __shared__ float Xs[16][132];
    __shared__ float Ws[16][132];

    const int tid = threadIdx.x;
    const int tr = tid >> 4;
    const int tc = tid & 15;

    float acc[8][8];
#pragma unroll
    for (int i = 0; i < 8; i++)
#pragma unroll
        for (int j = 0; j < 8; j++) acc[i][j] = 0.f;

    for (int k0 = 0; k0 < C_; k0 += 16) {
#pragma unroll
        for (int i = 0; i < 2; i++) {
            int idx = i * 256 + tid;
            int row = idx >> 2;
            int kc = (idx & 3) * 4;
            float4 v4 = *(const float4*)(x + (size_t)(m0 + row) * C_ + k0 + kc);
            Xs[kc + 0][row] = v4.x;
            Xs[kc + 1][row] = v4.y;
            Xs[kc + 2][row] = v4.z;
            Xs[kc + 3][row] = v4.w;
        }
#pragma unroll
        for (int i = 0; i < 2; i++) {
            int idx = i * 256 + tid;
            int kr = idx >> 5;
            int nc = (idx & 31) * 4;
            *(float4*)&Ws[kr][nc] = *(const float4*)(W + (size_t)(k0 + kr) * H_ + nc);
        }
        __syncthreads();

#pragma unroll
        for (int kk = 0; kk < 16; kk++) {
            float a[8], bv[8];
            *(float4*)&a[0] = *(const float4*)&Xs[kk][tr * 8];
            *(float4*)&a[4] = *(const float4*)&Xs[kk][tr * 8 + 4];
            *(float4*)&bv[0] = *(const float4*)&Ws[kk][tc * 8];
            *(float4*)&bv[4] = *(const float4*)&Ws[kk][tc * 8 + 4];
#pragma unroll
            for (int i = 0; i < 8; i++)
#pragma unroll
                for (int j = 0; j < 8; j++)
                    acc[i][j] = fmaf(a[i], bv[j], acc[i][j]);
        }
        __syncthreads();
    }

#pragma unroll
    for (int i = 0; i < 8; i++) {
        int row = m0 + tr * 8 + i;
        float4 o0 = make_float4(acc[i][0], acc[i][1], acc[i][2], acc[i][3]);
        float4 o1 = make_float4(acc[i][4], acc[i][5], acc[i][6], acc[i][7]);
        *(float4*)(out + (size_t)row * H_ + tc * 8) = o0;
        *(float4*)(out + (size_t)row * H_ + tc * 8 + 4) = o1;
    }
}

// ---------------------------------------------------------------------------
// Flash attention on tf32 mma.sync.m16n8k8.
// 128 CTAs (32 pairs x 4 batches). CTA processes q-tiles p and 63-p: constant
// 65 KV-tile visits. 8 warps: group 0 (warps 0-3) handles even KV tiles,
// group 1 odd (split-KV with private (m,l,acc), merged through smem at end).
// Each warp owns a 16-row strip of the 64-row q-tile. Q fragments live in
// registers; K/V converted to tf32 in smem; P->A via intra-quad shfl.
// ---------------------------------------------------------------------------
#define KSTRIDE 132
#define VSTRIDE 136
#define K0_OFF 0
#define V0_OFF (64 * KSTRIDE)                 // 8448
#define K1_OFF (V0_OFF + 64 * VSTRIDE)        // 17152
#define V1_OFF (K1_OFF + 64 * KSTRIDE)        // 25600
#define ML_OFF (V1_OFF + 64 * VSTRIDE)        // 34304
#define SMEM_WORDS (ML_OFF + 128)             // 34432

__device__ __forceinline__ unsigned f2tf(float f) {
    unsigned u;
    asm("cvt.rna.tf32.f32 %0, %1;" : "=r"(u) : "f"(f));
    return u;
}

__device__ __forceinline__ void mma8(float* d, const unsigned* a, const unsigned* b) {
    asm volatile(
        "mma.sync.aligned.m16n8k8.row.col.f32.tf32.tf32.f32 "
        "{%0,%1,%2,%3},{%4,%5,%6,%7},{%8,%9},{%0,%1,%2,%3};"
        : "+f"(d[0]), "+f"(d[1]), "+f"(d[2]), "+f"(d[3])
        : "r"(a[0]), "r"(a[1]), "r"(a[2]), "r"(a[3]), "r"(b[0]), "r"(b[1]));
}

__global__ __launch_bounds__(256, 1) void attn_kernel(float* __restrict__ out)
{
    extern __shared__ unsigned sm[];
    unsigned* const KsmA = sm + K0_OFF;
    float* const ML = (float*)(sm + ML_OFF);
    float* const ACC = (float*)(sm + K1_OFF);  // merge area aliases group-1 K

    const int tid  = threadIdx.x;
    const int lane = tid & 31;
    const int wid  = tid >> 5;
    const int g    = wid >> 2;       // KV parity group
    const int wq   = wid & 3;        // 16-row strip index
    const int quad = lane >> 2;      // 0..7
    const int qid  = lane & 3;       // 0..3
    const int rloc = wq * 16 + quad; // warp's low row within 64-row q-tile

    const int b = blockIdx.x & 3;
    const int p = blockIdx.x >> 2;
    const size_t base = (size_t)b * T_ * H_;

    unsigned* const Ks = sm + (g ? K1_OFF : K0_OFF);
    unsigned* const Vs = sm + (g ? V1_OFF : V0_OFF);
    const int barid = g + 1;

    // shfl sources for accumulator-layout -> A-operand-layout conversion
    const int src1 = (lane & ~3) | (qid >> 1);
    const int src2 = src1 + 2;
    const bool bsel = (qid & 1) != 0;

    for (int half = 0; half < 2; half++) {
        const int it = half ? (63 - p) : p;
        const int i0 = it * 64;

        // ---- stage Q (rows of g_k) into KsmA as tf32, build register frags
        __syncthreads();
        for (int idx = tid; idx < 64 * 32; idx += 256) {
            int row = idx >> 5;
            int d4 = (idx & 31) << 2;
            float4 v = *(const float4*)(g_k + base + (size_t)(i0 + row) * H_ + d4);
            unsigned* dst = KsmA + row * KSTRIDE + d4;
            dst[0] = f2tf(v.x); dst[1] = f2tf(v.y);
            dst[2] = f2tf(v.z); dst[3] = f2tf(v.w);
        }
        __syncthreads();
        unsigned qa[16][4];
#pragma unroll
        for (int kk = 0; kk < 16; kk++) {
            const unsigned* qp = KsmA + rloc * KSTRIDE + kk * 8 + qid;
            qa[kk][0] = qp[0];
            qa[kk][2] = qp[4];
            const unsigned* qp2 = qp + 8 * KSTRIDE;
            qa[kk][1] = qp2[0];
            qa[kk][3] = qp2[4];
        }
        __syncthreads();

        float oc[16][4];
#pragma unroll
        for (int nt = 0; nt < 16; nt++) {
            oc[nt][0] = 0.f; oc[nt][1] = 0.f; oc[nt][2] = 0.f; oc[nt][3] = 0.f;
        }
        float m_lo = -1e30f, m_hi = -1e30f, l_lo = 0.f, l_hi = 0.f;

        // ---- group loop over this group's KV tiles
        for (int jt = g; jt <= it; jt += 2) {
            const int j0 = jt * 64;
            asm volatile("bar.sync %0, 128;" :: "r"(barid) : "memory");
            // load K (rows of g_q) and V tiles, converting to tf32
            const int gtid = tid & 127;
            for (int idx = gtid; idx < 64 * 32; idx += 128) {
                int row = idx >> 5;
                int d4 = (idx & 31) << 2;
                float4 kv = *(const float4*)(g_q + base + (size_t)(j0 + row) * H_ + d4);
                unsigned* dk = Ks + row * KSTRIDE + d4;
                dk[0] = f2tf(kv.x); dk[1] = f2tf(kv.y);
                dk[2] = f2tf(kv.z); dk[3] = f2tf(kv.w);
                float4 vv = *(const float4*)(g_v + base + (size_t)(j0 + row) * H_ + d4);
                unsigned* dv = Vs + row * VSTRIDE + d4;
                dv[0] = f2tf(vv.x); dv[1] = f2tf(vv.y);
                dv[2] = f2tf(vv.z); dv[3] = f2tf(vv.w);
            }
            asm volatile("bar.sync %0, 128;" :: "r"(barid) : "memory");

            // ---- S = Q @ K^T  (warp: 16 x 64)
            float sc[8][4];
#pragma unroll
            for (int nt = 0; nt < 8; nt++) {
                sc[nt][0] = 0.f; sc[nt][1] = 0.f; sc[nt][2] = 0.f; sc[nt][3] = 0.f;
            }
#pragma unroll
            for (int kk = 0; kk < 16; kk++) {
#pragma unroll
                for (int nt = 0; nt < 8; nt++) {
                    unsigned bfr[2];
                    const unsigned* kp = Ks + (nt * 8 + quad) * KSTRIDE + kk * 8 + qid;
                    bfr[0] = kp[0];
                    bfr[1] = kp[4];
                    mma8(sc[nt], qa[kk], bfr);
                }
            }

            // ---- scale + causal mask (diagonal tile only)
            const bool diag = (jt == it);
#pragma unroll
            for (int nt = 0; nt < 8; nt++) {
#pragma unroll
                for (int c = 0; c < 4; c++) {
                    float v = sc[nt][c] * 0.03125f;
                    if (diag) {
                        int colL = nt * 8 + 2 * qid + (c & 1);
                        int rowL = rloc + ((c >> 1) << 3);
                        if (colL > rowL) v = -1e30f;
                    }
                    sc[nt][c] = v;
                }
            }

            // ---- online softmax (rows rloc / rloc+8; quad-wide reductions)
            float tm_lo = -1e30f, tm_hi = -1e30f;
#pragma unroll
            for (int nt = 0; nt < 8; nt++) {
                tm_lo = fmaxf(tm_lo, fmaxf(sc[nt][0], sc[nt][1]));
                tm_hi = fmaxf(tm_hi, fmaxf(sc[nt][2], sc[nt][3]));
            }
#pragma unroll
            for (int off = 1; off <= 2; off <<= 1) {
                tm_lo = fmaxf(tm_lo, __shfl_xor_sync(0xffffffffu, tm_lo, off));
                tm_hi = fmaxf(tm_hi, __shfl_xor_sync(0xffffffffu, tm_hi, off));
            }
            float mn_lo = fmaxf(m_lo, tm_lo), mn_hi = fmaxf(m_hi, tm_hi);
            float cf_lo = __expf(m_lo - mn_lo), cf_hi = __expf(m_hi - mn_hi);
            m_lo = mn_lo; m_hi = mn_hi;
            float sum_lo = 0.f, sum_hi = 0.f;
#pragma unroll
            for (int nt = 0; nt < 8; nt++) {
                sc[nt][0] = __expf(sc[nt][0] - mn_lo);
                sc[nt][1] = __expf(sc[nt][1] - mn_lo);
                sc[nt][2] = __expf(sc[nt][2] - mn_hi);
                sc[nt][3] = __expf(sc[nt][3] - mn_hi);
                sum_lo += sc[nt][0] + sc[nt][1];
                sum_hi += sc[nt][2] + sc[nt][3];
            }
#pragma unroll
            for (int off = 1; off <= 2; off <<= 1) {
                sum_lo += __shfl_xor_sync(0xffffffffu, sum_lo, off);
                sum_hi += __shfl_xor_sync(0xffffffffu, sum_hi, off);
            }
            l_lo = l_lo * cf_lo + sum_lo;
            l_hi = l_hi * cf_hi + sum_hi;
#pragma unroll
            for (int nt = 0; nt < 16; nt++) {
                oc[nt][0] *= cf_lo; oc[nt][1] *= cf_lo;
                oc[nt][2] *= cf_hi; oc[nt][3] *= cf_hi;
            }

            // ---- acc += P @ V  (P fragments built via intra-quad shfl)
#pragma unroll
            for (int kk = 0; kk < 8; kk++) {
                float v00 = __shfl_sync(0xffffffffu, sc[kk][0], src1);
                float v01 = __shfl_sync(0xffffffffu, sc[kk][1], src1);
                float v02 = __shfl_sync(0xffffffffu, sc[kk][2], src1);
                float v03 = __shfl_sync(0xffffffffu, sc[kk][3], src1);
                float v10 = __shfl_sync(0xffffffffu, sc[kk][0], src2);
                float v11 = __shfl_sync(0xffffffffu, sc[kk][1], src2);
                float v12 = __shfl_sync(0xffffffffu, sc[kk][2], src2);
                float v13 = __shfl_sync(0xffffffffu, sc[kk][3], src2);
                unsigned pa[4];
                pa[0] = f2tf(bsel ? v01 : v00);
                pa[1] = f2tf(bsel ? v03 : v02);
                pa[2] = f2tf(bsel ? v11 : v10);
                pa[3] = f2tf(bsel ? v13 : v12);
#pragma unroll
                for (int nt = 0; nt < 16; nt++) {
                    unsigned bfr[2];
                    const unsigned* vp = Vs + (kk * 8 + qid) * VSTRIDE + nt * 8 + quad;
                    bfr[0] = vp[0];
                    bfr[1] = vp[4 * VSTRIDE];
                    mma8(oc[nt], pa, bfr);
                }
            }
        }

        // ---- merge the two split-KV partials, write output
        __syncthreads();
        if (g == 1) {
#pragma unroll
            for (int nt = 0; nt < 16; nt++) {
                float* a0 = ACC + rloc * KSTRIDE + nt * 8 + 2 * qid;
                a0[0] = oc[nt][0]; a0[1] = oc[nt][1];
                float* a1 = a0 + 8 * KSTRIDE;
                a1[0] = oc[nt][2]; a1[1] = oc[nt][3];
            }
            if (qid == 0) {
                ML[rloc * 2 + 0] = m_lo;
                ML[rloc * 2 + 1] = l_lo;
                ML[(rloc + 8) * 2 + 0] = m_hi;
                ML[(rloc + 8) * 2 + 1] = l_hi;
            }
        }
        __syncthreads();
        if (g == 0) {
            float mB_lo = ML[rloc * 2], lB_lo = ML[rloc * 2 + 1];
            float mB_hi = ML[(rloc + 8) * 2], lB_hi = ML[(rloc + 8) * 2 + 1];
            float ms_lo = fmaxf(m_lo, mB_lo), ms_hi = fmaxf(m_hi, mB_hi);
            float ca_lo = __expf(m_lo - ms_lo), cb_lo = __expf(mB_lo - ms_lo);
            float ca_hi = __expf(m_hi - ms_hi), cb_hi = __expf(mB_hi - ms_hi);
            float li_lo = 1.f / (l_lo * ca_lo + lB_lo * cb_lo);
            float li_hi = 1.f / (l_hi * ca_hi + lB_hi * cb_hi);
#pragma unroll
            for (int nt = 0; nt < 16; nt++) {
                const float* a0 = ACC + rloc * KSTRIDE + nt * 8 + 2 * qid;
                const float* a1 = a0 + 8 * KSTRIDE;
                float2 o0, o1;
                o0.x = (oc[nt][0] * ca_lo + a0[0] * cb_lo) * li_lo;
                o0.y = (oc[nt][1] * ca_lo + a0[1] * cb_lo) * li_lo;
                o1.x = (oc[nt][2] * ca_hi + a1[0] * cb_hi) * li_hi;
                o1.y = (oc[nt][3] * ca_hi + a1[1] * cb_hi) * li_hi;
                *(float2*)(out + base + (size_t)(i0 + rloc) * H_ + nt * 8 + 2 * qid) = o0;
                *(float2*)(out + base + (size_t)(i0 + rloc + 8) * H_ + nt * 8 + 2 * qid) = o1;
            }
        }
    }
}

extern "C" void kernel_launch(void* const* d_in, const int* in_sizes, int n_in,
                              void* d_out, int out_size)
{
    const float* x  = (const float*)d_in[0];
    const float* Wk = (const float*)d_in[1];
    const float* Wq = (const float*)d_in[2];
    const float* Wv = (const float*)d_in[3];
    float* out = (float*)d_out;

    dim3 pgrid(M_ / 128, 3);
    proj_kernel<<<pgrid, 256>>>(x, Wk, Wq, Wv);

    const int smem_bytes = SMEM_WORDS * (int)sizeof(unsigned);
    cudaFuncSetAttribute(attn_kernel,
                         cudaFuncAttributeMaxDynamicSharedMemorySize, smem_bytes);
    attn_kernel<<<dim3((T_ / 128) * B_), 256, smem_bytes>>>(out);
}